// round 2
// baseline (speedup 1.0000x reference)
#include <cuda_runtime.h>
#include <cuda_bf16.h>

#define N_IMG   8192
#define TSTRIDE 33   // smem row stride (32 cols + 1 pad)

__global__ __launch_bounds__(256, 4)
void quan2d_kernel(const float* __restrict__ x,
                   const float* __restrict__ w,
                   float* __restrict__ out)
{
    __shared__ float tile[32 * TSTRIDE];
    __shared__ float gc[8], gs[8];

    const int tid = threadIdx.x;
    const int img = blockIdx.x;

    // Per-block gate coefficients: RY(theta) -> cos(theta/2), sin(theta/2)
    if (tid < 8) {
        float sv, cv;
        sincosf(w[tid] * 0.5f, &sv, &cv);
        gc[tid] = cv;
        gs[tid] = sv;
    }

    // Coalesced image load: 256 threads x float4 = 1024 floats = one 32x32 image
    {
        float4 v4 = reinterpret_cast<const float4*>(x)[img * 256 + tid];
        int r  = tid >> 3;          // row 0..31
        int c4 = (tid & 7) << 2;    // col 0,4,...,28
        float* dst = &tile[r * TSTRIDE + c4];
        dst[0] = v4.x; dst[1] = v4.y; dst[2] = v4.z; dst[3] = v4.w;
    }
    __syncthreads();

    // Patch (ph, pw): rows 2ph..2ph+3, cols 2pw..2pw+3 of zero-padded 34x34 image.
    const int ph = tid >> 4;
    const int pw = tid & 15;
    const int r0 = ph * 2;
    const int c0 = pw * 2;

    // Amplitudes: flat index j = dr*4 + dc; wire0 = MSB (mask 8), wire q -> mask 8>>q
    float a[16];
#pragma unroll
    for (int dr = 0; dr < 4; ++dr) {
#pragma unroll
        for (int dc = 0; dc < 4; ++dc) {
            int rr = r0 + dr, cc = c0 + dc;
            a[dr * 4 + dc] = (rr < 32 && cc < 32) ? tile[rr * TSTRIDE + cc] : 0.0f;
        }
    }

    // RY on qubit with bit-mask m: new0 = c*t0 - s*t1 ; new1 = s*t0 + c*t1
    auto ry = [&](int m, float cv, float sv) {
#pragma unroll
        for (int j = 0; j < 16; ++j) {
            if (j & m) continue;
            float t0 = a[j];
            float t1 = a[j | m];
            a[j]     = fmaf(cv, t0, -sv * t1);
            a[j | m] = fmaf(sv, t0,  cv * t1);
        }
    };
    // CNOT(control mask cb, target mask tb): swap within control=1
    auto cnot = [&](int cb, int tb) {
#pragma unroll
        for (int j = 0; j < 16; ++j) {
            if ((j & cb) && !(j & tb)) {
                float t = a[j];
                a[j] = a[j | tb];
                a[j | tb] = t;
            }
        }
    };

    // Layer 1: RY(weights[0..3]) on qubits 0..3  (qubit i -> mask 8>>i)
    ry(8, gc[0], gs[0]);
    ry(4, gc[1], gs[1]);
    ry(2, gc[2], gs[2]);
    ry(1, gc[3], gs[3]);

    // CNOT ring: (0,1), (1,2), (2,3), (3,0)
    cnot(8, 4);
    cnot(4, 2);
    cnot(2, 1);
    cnot(1, 8);

    // Layer 2: RY(weights[4..7])
    ry(8, gc[4], gs[4]);
    ry(4, gc[5], gs[5]);
    ry(2, gc[6], gs[6]);
    ry(1, gc[7], gs[7]);

    // Circuit is orthogonal: ||u|| = ||v||, so normalize via sum of squares of u.
    float sq[16];
#pragma unroll
    for (int j = 0; j < 16; ++j) sq[j] = a[j] * a[j];

    float nrm = 0.0f;
#pragma unroll
    for (int j = 0; j < 16; ++j) nrm += sq[j];

    // <Z_w> = nrm - 2 * sum_{j with bit_w set} sq[j], then / nrm
    float s0 = 0.0f, s1 = 0.0f, s2 = 0.0f, s3 = 0.0f;
#pragma unroll
    for (int j = 0; j < 16; ++j) {
        if (j & 8) s0 += sq[j];
        if (j & 4) s1 += sq[j];
        if (j & 2) s2 += sq[j];
        if (j & 1) s3 += sq[j];
    }

    float inv = 1.0f / nrm;
    float4 o;
    o.x = fmaf(-2.0f * s0, inv, 1.0f);
    o.y = fmaf(-2.0f * s1, inv, 1.0f);
    o.z = fmaf(-2.0f * s2, inv, 1.0f);
    o.w = fmaf(-2.0f * s3, inv, 1.0f);

    // out[img, p*4 + w], p = ph*16+pw = tid  -> coalesced float4 store
    reinterpret_cast<float4*>(out)[img * 256 + tid] = o;
}

extern "C" void kernel_launch(void* const* d_in, const int* in_sizes, int n_in,
                              void* d_out, int out_size)
{
    // Defensive input-order resolution: x has 8388608 elements, weights has 8.
    const float* x = (const float*)d_in[0];
    const float* w = (const float*)d_in[1];
    if (n_in >= 2 && in_sizes[0] == 8) {
        x = (const float*)d_in[1];
        w = (const float*)d_in[0];
    }
    float* out = (float*)d_out;

    quan2d_kernel<<<N_IMG, 256>>>(x, w, out);
}

// round 3
// speedup vs baseline: 1.1687x; 1.1687x over previous
#include <cuda_runtime.h>
#include <cuda_bf16.h>

#define TSTRIDE 33   // smem row stride (32 cols + 1 pad)

using ull = unsigned long long;

// ---- packed f32x2 helpers (sm_100+ PTX; ptxas never auto-fuses these) ----
__device__ __forceinline__ ull pack2(float lo, float hi) {
    ull r;
    asm("mov.b64 %0, {%1, %2};" : "=l"(r)
        : "r"(__float_as_uint(lo)), "r"(__float_as_uint(hi)));
    return r;
}
__device__ __forceinline__ void unpack2(ull v, float& lo, float& hi) {
    unsigned a, b;
    asm("mov.b64 {%0, %1}, %2;" : "=r"(a), "=r"(b) : "l"(v));
    lo = __uint_as_float(a); hi = __uint_as_float(b);
}
__device__ __forceinline__ ull ffma2(ull a, ull b, ull c) {
    ull d; asm("fma.rn.f32x2 %0, %1, %2, %3;" : "=l"(d) : "l"(a), "l"(b), "l"(c));
    return d;
}
__device__ __forceinline__ ull fmul2(ull a, ull b) {
    ull d; asm("mul.rn.f32x2 %0, %1, %2;" : "=l"(d) : "l"(a), "l"(b));
    return d;
}
__device__ __forceinline__ ull fadd2(ull a, ull b) {
    ull d; asm("add.rn.f32x2 %0, %1, %2;" : "=l"(d) : "l"(a), "l"(b));
    return d;
}

__global__ __launch_bounds__(256, 3)
void quan2d_kernel(const float4* __restrict__ x4,
                   const float* __restrict__ w,
                   float4* __restrict__ out4)
{
    __shared__ float tile[2][32 * TSTRIDE];
    __shared__ float gc[8], gs[8];

    const int tid  = threadIdx.x;
    const int img0 = blockIdx.x * 2;   // this block handles images img0, img0+1

    if (tid < 8) {
        float sv, cv;
        sincosf(w[tid] * 0.5f, &sv, &cv);
        gc[tid] = cv; gs[tid] = sv;
    }

    // Coalesced load of both 32x32 images (256 threads x 2 float4)
    {
        float4 v0 = x4[img0 * 256 + tid];
        float4 v1 = x4[(img0 + 1) * 256 + tid];
        int r = tid >> 3, c4 = (tid & 7) << 2;
        float* d0 = &tile[0][r * TSTRIDE + c4];
        d0[0] = v0.x; d0[1] = v0.y; d0[2] = v0.z; d0[3] = v0.w;
        float* d1 = &tile[1][r * TSTRIDE + c4];
        d1[0] = v1.x; d1[1] = v1.y; d1[2] = v1.z; d1[3] = v1.w;
    }
    __syncthreads();

    // Patch tid = (ph, pw); rows 2ph..2ph+3, cols 2pw..2pw+3 of zero-padded 34x34
    const int ph = tid >> 4, pw = tid & 15;
    const int r0 = ph * 2,   c0 = pw * 2;

    // Amplitudes for BOTH images packed: a[j] = { img0 lane, img1 lane }
    // flat j = dr*4 + dc; wire0 = MSB (mask 8), wire q -> mask 8>>q
    ull a[16];
#pragma unroll
    for (int dr = 0; dr < 4; ++dr)
#pragma unroll
        for (int dc = 0; dc < 4; ++dc) {
            int rr = r0 + dr, cc = c0 + dc;
            float v0 = 0.0f, v1 = 0.0f;
            if (rr < 32 && cc < 32) {
                v0 = tile[0][rr * TSTRIDE + cc];
                v1 = tile[1][rr * TSTRIDE + cc];
            }
            a[dr * 4 + dc] = pack2(v0, v1);
        }

    // RY on qubit mask m: new0 = c*t0 - s*t1 ; new1 = s*t0 + c*t1 (packed)
    auto ry = [&](int m, int gi) {
        float c = gc[gi], s = gs[gi];
        ull c2 = pack2(c, c), s2 = pack2(s, s), ns2 = pack2(-s, -s);
#pragma unroll
        for (int j = 0; j < 16; ++j) {
            if (j & m) continue;
            ull t0 = a[j], t1 = a[j | m];
            a[j]     = ffma2(c2, t0, fmul2(ns2, t1));
            a[j | m] = ffma2(s2, t0, fmul2(c2, t1));
        }
    };
    // CNOT = register permutation (free)
    auto cnot = [&](int cb, int tb) {
#pragma unroll
        for (int j = 0; j < 16; ++j)
            if ((j & cb) && !(j & tb)) { ull t = a[j]; a[j] = a[j | tb]; a[j | tb] = t; }
    };

    ry(8, 0); ry(4, 1); ry(2, 2); ry(1, 3);
    cnot(8, 4); cnot(4, 2); cnot(2, 1); cnot(1, 8);
    ry(8, 4); ry(4, 5); ry(2, 6); ry(1, 7);

    // Squares fused into group sums:
    //   G[g] = sum of a[j]^2 over j with (bit3,bit2) = g   (j = g*4 + k)
    //   H[g] = sum of a[j]^2 over j with (bit1,bit0) = g   (j = k*4 + g)
    ull G[4], H[4];
#pragma unroll
    for (int g = 0; g < 4; ++g) {
        ull acc = fmul2(a[g * 4], a[g * 4]);
#pragma unroll
        for (int k = 1; k < 4; ++k) acc = ffma2(a[g * 4 + k], a[g * 4 + k], acc);
        G[g] = acc;
        ull acc2 = fmul2(a[g], a[g]);
#pragma unroll
        for (int k = 1; k < 4; ++k) acc2 = ffma2(a[k * 4 + g], a[k * 4 + g], acc2);
        H[g] = acc2;
    }
    ull nrm2 = fadd2(fadd2(G[0], G[1]), fadd2(G[2], G[3]));
    ull s0p = fadd2(G[2], G[3]);   // wire0 (bit3 set)
    ull s1p = fadd2(G[1], G[3]);   // wire1 (bit2 set)
    ull s2p = fadd2(H[2], H[3]);   // wire2 (bit1 set)
    ull s3p = fadd2(H[1], H[3]);   // wire3 (bit0 set)

    // <Z_w> = 1 - 2*s_w/nrm  (circuit is orthogonal: ||u|| = ||psi_in||)
    float n0, n1;
    unpack2(nrm2, n0, n1);
    float inv0 = __fdividef(1.0f, n0);
    float inv1 = __fdividef(1.0f, n1);
    ull m2inv = fmul2(pack2(inv0, inv1), pack2(-2.0f, -2.0f));
    ull ones  = pack2(1.0f, 1.0f);

    ull z0 = ffma2(s0p, m2inv, ones);
    ull z1 = ffma2(s1p, m2inv, ones);
    ull z2 = ffma2(s2p, m2inv, ones);
    ull z3 = ffma2(s3p, m2inv, ones);

    float4 o0, o1;
    unpack2(z0, o0.x, o1.x);
    unpack2(z1, o0.y, o1.y);
    unpack2(z2, o0.z, o1.z);
    unpack2(z3, o0.w, o1.w);

    // out[img, p*4 + w] with p = tid -> coalesced float4 stores
    out4[img0 * 256 + tid]       = o0;
    out4[(img0 + 1) * 256 + tid] = o1;
}

extern "C" void kernel_launch(void* const* d_in, const int* in_sizes, int n_in,
                              void* d_out, int out_size)
{
    const float* x = (const float*)d_in[0];
    const float* w = (const float*)d_in[1];
    if (n_in >= 2 && in_sizes[0] == 8) {   // defensive input-order resolution
        x = (const float*)d_in[1];
        w = (const float*)d_in[0];
    }
    quan2d_kernel<<<4096, 256>>>((const float4*)x, w, (float4*)d_out);
}

// round 4
// speedup vs baseline: 1.5801x; 1.3520x over previous
#include <cuda_runtime.h>
#include <cuda_bf16.h>

#define TSTRIDE 33   // smem row stride (32 cols + 1 pad)

using ull = unsigned long long;

// ---- packed f32x2 helpers (sm_100+ PTX; ptxas never auto-fuses these) ----
__device__ __forceinline__ ull pack2(float lo, float hi) {
    ull r;
    asm("mov.b64 %0, {%1, %2};" : "=l"(r)
        : "r"(__float_as_uint(lo)), "r"(__float_as_uint(hi)));
    return r;
}
__device__ __forceinline__ void unpack2(ull v, float& lo, float& hi) {
    unsigned a, b;
    asm("mov.b64 {%0, %1}, %2;" : "=r"(a), "=r"(b) : "l"(v));
    lo = __uint_as_float(a); hi = __uint_as_float(b);
}
__device__ __forceinline__ ull ffma2(ull a, ull b, ull c) {
    ull d; asm("fma.rn.f32x2 %0, %1, %2, %3;" : "=l"(d) : "l"(a), "l"(b), "l"(c));
    return d;
}
__device__ __forceinline__ ull fmul2(ull a, ull b) {
    ull d; asm("mul.rn.f32x2 %0, %1, %2;" : "=l"(d) : "l"(a), "l"(b));
    return d;
}
__device__ __forceinline__ ull fadd2(ull a, ull b) {
    ull d; asm("add.rn.f32x2 %0, %1, %2;" : "=l"(d) : "l"(a), "l"(b));
    return d;
}

__global__ __launch_bounds__(256, 4)
void quan2d_kernel(const float4* __restrict__ x4,
                   const float* __restrict__ w,
                   float4* __restrict__ out4)
{
    __shared__ float tile[2][32 * TSTRIDE];
    __shared__ float gr[8];   // tan(theta/2); cosine factor cancels in <Z> ratio

    const int tid  = threadIdx.x;
    const int img0 = blockIdx.x * 2;   // this block handles images img0, img0+1

    if (tid < 8) {
        float sv, cv;
        sincosf(w[tid] * 0.5f, &sv, &cv);
        gr[tid] = __fdividef(sv, cv);
    }

    // Coalesced load of both 32x32 images (256 threads x 2 float4)
    {
        float4 v0 = x4[img0 * 256 + tid];
        float4 v1 = x4[(img0 + 1) * 256 + tid];
        int r = tid >> 3, c4 = (tid & 7) << 2;
        float* d0 = &tile[0][r * TSTRIDE + c4];
        d0[0] = v0.x; d0[1] = v0.y; d0[2] = v0.z; d0[3] = v0.w;
        float* d1 = &tile[1][r * TSTRIDE + c4];
        d1[0] = v1.x; d1[1] = v1.y; d1[2] = v1.z; d1[3] = v1.w;
    }
    __syncthreads();

    // Patch tid = (ph, pw); rows 2ph..2ph+3, cols 2pw..2pw+3 of zero-padded 34x34
    const int ph = tid >> 4, pw = tid & 15;
    const int r0 = ph * 2,   c0 = pw * 2;

    // Amplitudes for BOTH images packed: a[j] = { img0 lane, img1 lane }
    // flat j = dr*4 + dc; wire0 = MSB (mask 8), wire q -> mask 8>>q
    ull a[16];
#pragma unroll
    for (int dr = 0; dr < 4; ++dr)
#pragma unroll
        for (int dc = 0; dc < 4; ++dc) {
            int rr = r0 + dr, cc = c0 + dc;
            float v0 = 0.0f, v1 = 0.0f;
            if (rr < 32 && cc < 32) {
                v0 = tile[0][rr * TSTRIDE + cc];
                v1 = tile[1][rr * TSTRIDE + cc];
            }
            a[dr * 4 + dc] = pack2(v0, v1);
        }

    // RY (tangent form, cosine deferred): new0 = t0 - r*t1 ; new1 = r*t0 + t1
    // The dropped factor cos(theta/2) multiplies the whole state and cancels
    // in <Z> = 1 - 2*s/nrm (both s and nrm scale by (prod c)^2).
    auto ry = [&](int m, int gi) {
        float r = gr[gi];
        ull r2  = pack2(r, r);
        ull nr2 = pack2(-r, -r);
#pragma unroll
        for (int j = 0; j < 16; ++j) {
            if (j & m) continue;
            ull t0 = a[j], t1 = a[j | m];
            a[j]     = ffma2(nr2, t1, t0);   // t0 - r*t1
            a[j | m] = ffma2(r2,  t0, t1);   // r*t0 + t1
        }
    };
    // CNOT = register permutation (free)
    auto cnot = [&](int cb, int tb) {
#pragma unroll
        for (int j = 0; j < 16; ++j)
            if ((j & cb) && !(j & tb)) { ull t = a[j]; a[j] = a[j | tb]; a[j | tb] = t; }
    };

    ry(8, 0); ry(4, 1); ry(2, 2); ry(1, 3);
    cnot(8, 4); cnot(4, 2); cnot(2, 1); cnot(1, 8);
    ry(8, 4); ry(4, 5); ry(2, 6); ry(1, 7);

    // Squares fused into group sums:
    //   G[g] = sum of a[j]^2 over j with (bit3,bit2) = g   (j = g*4 + k)
    //   H[g] = sum of a[j]^2 over j with (bit1,bit0) = g   (j = k*4 + g)
    ull G[4], H[4];
#pragma unroll
    for (int g = 0; g < 4; ++g) {
        ull acc = fmul2(a[g * 4], a[g * 4]);
#pragma unroll
        for (int k = 1; k < 4; ++k) acc = ffma2(a[g * 4 + k], a[g * 4 + k], acc);
        G[g] = acc;
        ull acc2 = fmul2(a[g], a[g]);
#pragma unroll
        for (int k = 1; k < 4; ++k) acc2 = ffma2(a[k * 4 + g], a[k * 4 + g], acc2);
        H[g] = acc2;
    }
    ull nrm2 = fadd2(fadd2(G[0], G[1]), fadd2(G[2], G[3]));
    ull s0p = fadd2(G[2], G[3]);   // wire0 (bit3 set)
    ull s1p = fadd2(G[1], G[3]);   // wire1 (bit2 set)
    ull s2p = fadd2(H[2], H[3]);   // wire2 (bit1 set)
    ull s3p = fadd2(H[1], H[3]);   // wire3 (bit0 set)

    // <Z_w> = 1 - 2*s_w/nrm
    float n0, n1;
    unpack2(nrm2, n0, n1);
    float inv0 = __fdividef(-2.0f, n0);
    float inv1 = __fdividef(-2.0f, n1);
    ull m2inv = pack2(inv0, inv1);
    ull ones  = pack2(1.0f, 1.0f);

    ull z0 = ffma2(s0p, m2inv, ones);
    ull z1 = ffma2(s1p, m2inv, ones);
    ull z2 = ffma2(s2p, m2inv, ones);
    ull z3 = ffma2(s3p, m2inv, ones);

    float4 o0, o1;
    unpack2(z0, o0.x, o1.x);
    unpack2(z1, o0.y, o1.y);
    unpack2(z2, o0.z, o1.z);
    unpack2(z3, o0.w, o1.w);

    // out[img, p*4 + w] with p = tid -> coalesced float4 stores
    out4[img0 * 256 + tid]       = o0;
    out4[(img0 + 1) * 256 + tid] = o1;
}

extern "C" void kernel_launch(void* const* d_in, const int* in_sizes, int n_in,
                              void* d_out, int out_size)
{
    const float* x = (const float*)d_in[0];
    const float* w = (const float*)d_in[1];
    if (n_in >= 2 && in_sizes[0] == 8) {   // defensive input-order resolution
        x = (const float*)d_in[1];
        w = (const float*)d_in[0];
    }
    quan2d_kernel<<<4096, 256>>>((const float4*)x, w, (float4*)d_out);
}

// round 7
// speedup vs baseline: 1.5945x; 1.0091x over previous
#include <cuda_runtime.h>
#include <cuda_bf16.h>

#define TS 36          // smem row stride in floats (34 cols used + pad; 144B keeps float4 alignment)

using ull = unsigned long long;

// ---- packed f32x2 helpers (sm_100+ PTX; ptxas never auto-fuses these) ----
__device__ __forceinline__ ull pack2(float lo, float hi) {
    ull r;
    asm("mov.b64 %0, {%1, %2};" : "=l"(r)
        : "r"(__float_as_uint(lo)), "r"(__float_as_uint(hi)));
    return r;
}
__device__ __forceinline__ void unpack2(ull v, float& lo, float& hi) {
    unsigned a, b;
    asm("mov.b64 {%0, %1}, %2;" : "=r"(a), "=r"(b) : "l"(v));
    lo = __uint_as_float(a); hi = __uint_as_float(b);
}
__device__ __forceinline__ ull ffma2(ull a, ull b, ull c) {
    ull d; asm("fma.rn.f32x2 %0, %1, %2, %3;" : "=l"(d) : "l"(a), "l"(b), "l"(c));
    return d;
}
__device__ __forceinline__ ull fmul2(ull a, ull b) {
    ull d; asm("mul.rn.f32x2 %0, %1, %2;" : "=l"(d) : "l"(a), "l"(b));
    return d;
}
__device__ __forceinline__ ull fadd2(ull a, ull b) {
    ull d; asm("add.rn.f32x2 %0, %1, %2;" : "=l"(d) : "l"(a), "l"(b));
    return d;
}

__global__ __launch_bounds__(256, 5)
void quan2d_kernel(const float4* __restrict__ x4,
                   const float* __restrict__ w,
                   float4* __restrict__ out4)
{
    // 34x34 zero-padded image tiles (rows 32-33 and cols 32-33 are zeros),
    // so the patch gather needs NO bounds predicates.
    __shared__ float tile[2][34 * TS];
    __shared__ float gr[8];   // tan(theta/2); cosine factor cancels in <Z> ratio

    const int tid  = threadIdx.x;
    const int img0 = blockIdx.x * 2;

    if (tid < 8) {
        float sv, cv;
        sincosf(w[tid] * 0.5f, &sv, &cv);
        gr[tid] = __fdividef(sv, cv);
    }

    // Zero the padding: cols 32..35 for rows 0..33 (34 float4 per image),
    // rows 32..33 cols 0..31 (16 float4 per image). 100 STS.128 total.
    {
        const float4 z4 = make_float4(0.f, 0.f, 0.f, 0.f);
        if (tid < 68) {                       // right border: img = tid&1, row = tid>>1
            int im = tid & 1, r = tid >> 1;
            *reinterpret_cast<float4*>(&tile[im][r * TS + 32]) = z4;
        } else if (tid < 100) {               // bottom rows: 32 float4 covers 2 rows x 8 per image
            int t = tid - 68;                 // 0..31
            int im = t >> 4;                  // 0..1
            int q  = t & 15;                  // 0..15 -> row 32 + (q>>3), col4 = (q&7)*4
            *reinterpret_cast<float4*>(&tile[im][(32 + (q >> 3)) * TS + ((q & 7) << 2)]) = z4;
        }
    }

    // Coalesced load of both 32x32 images (256 threads x 2 float4, STS.128)
    {
        float4 v0 = x4[img0 * 256 + tid];
        float4 v1 = x4[(img0 + 1) * 256 + tid];
        int r = tid >> 3, c4 = (tid & 7) << 2;
        *reinterpret_cast<float4*>(&tile[0][r * TS + c4]) = v0;
        *reinterpret_cast<float4*>(&tile[1][r * TS + c4]) = v1;
    }
    __syncthreads();

    // Patch tid = (ph, pw); rows 2ph..2ph+3, cols 2pw..2pw+3 of the padded 34x34.
    const int ph = tid >> 4, pw = tid & 15;
    const int base = (ph * 2) * TS + (pw * 2);   // even col -> 8B aligned -> LDS.64

    // Amplitudes for BOTH images packed: a[j] = { img0 lane, img1 lane }
    // flat j = dr*4 + dc; wire0 = MSB (mask 8), wire q -> mask 8>>q
    ull a[16];
#pragma unroll
    for (int dr = 0; dr < 4; ++dr) {
        const float2* r0p = reinterpret_cast<const float2*>(&tile[0][base + dr * TS]);
        const float2* r1p = reinterpret_cast<const float2*>(&tile[1][base + dr * TS]);
        float2 p0a = r0p[0], p0b = r0p[1];     // img0: cols c0..c0+3
        float2 p1a = r1p[0], p1b = r1p[1];     // img1
        a[dr * 4 + 0] = pack2(p0a.x, p1a.x);
        a[dr * 4 + 1] = pack2(p0a.y, p1a.y);
        a[dr * 4 + 2] = pack2(p0b.x, p1b.x);
        a[dr * 4 + 3] = pack2(p0b.y, p1b.y);
    }

    // RY (tangent form, cosine deferred): new0 = t0 - r*t1 ; new1 = r*t0 + t1
    // Dropped cos(theta/2) is a global state factor that cancels in <Z> = 1 - 2*s/nrm.
    auto ry = [&](int m, int gi) {
        float r = gr[gi];
        ull r2  = pack2(r, r);
        ull nr2 = pack2(-r, -r);
#pragma unroll
        for (int j = 0; j < 16; ++j) {
            if (j & m) continue;
            ull t0 = a[j], t1 = a[j | m];
            a[j]     = ffma2(nr2, t1, t0);   // t0 - r*t1
            a[j | m] = ffma2(r2,  t0, t1);   // r*t0 + t1
        }
    };
    // CNOT = register permutation (free)
    auto cnot = [&](int cb, int tb) {
#pragma unroll
        for (int j = 0; j < 16; ++j)
            if ((j & cb) && !(j & tb)) { ull t = a[j]; a[j] = a[j | tb]; a[j | tb] = t; }
    };

    ry(8, 0); ry(4, 1); ry(2, 2); ry(1, 3);
    cnot(8, 4); cnot(4, 2); cnot(2, 1); cnot(1, 8);
    ry(8, 4); ry(4, 5); ry(2, 6); ry(1, 7);

    // Group sums of squares:
    //   G[g] = sum a[j]^2 over j with (bit3,bit2) = g   (j = g*4 + k)
    //   H[g] = sum a[j]^2 over j with (bit1,bit0) = g   (j = k*4 + g)
    ull G[4], H[4];
#pragma unroll
    for (int g = 0; g < 4; ++g) {
        ull acc = fmul2(a[g * 4], a[g * 4]);
#pragma unroll
        for (int k = 1; k < 4; ++k) acc = ffma2(a[g * 4 + k], a[g * 4 + k], acc);
        G[g] = acc;
        ull acc2 = fmul2(a[g], a[g]);
#pragma unroll
        for (int k = 1; k < 4; ++k) acc2 = ffma2(a[k * 4 + g], a[k * 4 + g], acc2);
        H[g] = acc2;
    }
    ull nrm2 = fadd2(fadd2(G[0], G[1]), fadd2(G[2], G[3]));
    ull s0p = fadd2(G[2], G[3]);   // wire0 (bit3 set)
    ull s1p = fadd2(G[1], G[3]);   // wire1 (bit2 set)
    ull s2p = fadd2(H[2], H[3]);   // wire2 (bit1 set)
    ull s3p = fadd2(H[1], H[3]);   // wire3 (bit0 set)

    // <Z_w> = 1 - 2*s_w/nrm
    float n0, n1;
    unpack2(nrm2, n0, n1);
    float inv0 = __fdividef(-2.0f, n0);
    float inv1 = __fdividef(-2.0f, n1);
    ull m2inv = pack2(inv0, inv1);
    ull ones  = pack2(1.0f, 1.0f);

    ull z0 = ffma2(s0p, m2inv, ones);
    ull z1 = ffma2(s1p, m2inv, ones);
    ull z2 = ffma2(s2p, m2inv, ones);
    ull z3 = ffma2(s3p, m2inv, ones);

    float4 o0, o1;
    unpack2(z0, o0.x, o1.x);
    unpack2(z1, o0.y, o1.y);
    unpack2(z2, o0.z, o1.z);
    unpack2(z3, o0.w, o1.w);

    // out[img, p*4 + w] with p = tid -> coalesced float4 stores
    out4[img0 * 256 + tid]       = o0;
    out4[(img0 + 1) * 256 + tid] = o1;
}

extern "C" void kernel_launch(void* const* d_in, const int* in_sizes, int n_in,
                              void* d_out, int out_size)
{
    const float* x = (const float*)d_in[0];
    const float* w = (const float*)d_in[1];
    if (n_in >= 2 && in_sizes[0] == 8) {   // defensive input-order resolution
        x = (const float*)d_in[1];
        w = (const float*)d_in[0];
    }
    quan2d_kernel<<<4096, 256>>>((const float4*)x, w, (float4*)d_out);
}